// round 1
// baseline (speedup 1.0000x reference)
#include <cuda_runtime.h>
#include <math.h>

#define BATCH 2
#define SEQ   2048
#define DMODEL 2048
#define NH    32
#define NKV   8
#define HD    64
#define NREP  (NH / NKV)

// ---------------------------------------------------------------------------
// Scratch (device globals — no allocation allowed)
// ---------------------------------------------------------------------------
__device__ float g_Q[(size_t)BATCH * SEQ * NH * HD];    // [B,S,NH,HD]
__device__ float g_K[(size_t)BATCH * SEQ * NKV * HD];   // [B,S,NKV,HD]
__device__ float g_V[(size_t)BATCH * SEQ * NKV * HD];
__device__ float g_A[(size_t)BATCH * SEQ * NH * HD];    // attn output [B,S,NH*HD]

// ---------------------------------------------------------------------------
// SGEMM: C[M,N] = A[M,K] * B[N,K]^T   (both row-major, K contiguous)
// 128x128 block tile, BK=16, 256 threads, 8x8 per-thread tile.
// M,N divisible by 128; K divisible by 16 (true for all 4 calls).
// ---------------------------------------------------------------------------
#define BM 128
#define BN 128
#define BK 16

__global__ __launch_bounds__(256) void sgemm_nt(
    const float* __restrict__ A, const float* __restrict__ B,
    float* __restrict__ C, int M, int N, int K)
{
    __shared__ float As[BK][BM];
    __shared__ float Bs[BK][BN];

    const int tid = threadIdx.x;
    const int bm = blockIdx.y * BM;
    const int bn = blockIdx.x * BN;
    const int tx = tid & 15;      // 0..15 -> n
    const int ty = tid >> 4;      // 0..15 -> m

    float acc[8][8];
#pragma unroll
    for (int i = 0; i < 8; i++)
#pragma unroll
        for (int j = 0; j < 8; j++) acc[i][j] = 0.0f;

    for (int k0 = 0; k0 < K; k0 += BK) {
        // Stage tiles (transposed into [k][m]/[k][n] for conflict-free compute reads).
#pragma unroll
        for (int i = 0; i < 2; i++) {
            int f = tid + i * 256;          // 0..511 float4 slots
            int r = f >> 2;                 // row within 128
            int c = (f & 3) << 2;           // k offset 0/4/8/12
            float4 av = *(const float4*)(A + (size_t)(bm + r) * K + k0 + c);
            As[c + 0][r] = av.x; As[c + 1][r] = av.y;
            As[c + 2][r] = av.z; As[c + 3][r] = av.w;
            float4 bv = *(const float4*)(B + (size_t)(bn + r) * K + k0 + c);
            Bs[c + 0][r] = bv.x; Bs[c + 1][r] = bv.y;
            Bs[c + 2][r] = bv.z; Bs[c + 3][r] = bv.w;
        }
        __syncthreads();

#pragma unroll
        for (int kk = 0; kk < BK; kk++) {
            float a_f[8], b_f[8];
            *(float4*)&a_f[0] = *(const float4*)&As[kk][ty * 8];
            *(float4*)&a_f[4] = *(const float4*)&As[kk][ty * 8 + 4];
            *(float4*)&b_f[0] = *(const float4*)&Bs[kk][tx * 8];
            *(float4*)&b_f[4] = *(const float4*)&Bs[kk][tx * 8 + 4];
#pragma unroll
            for (int i = 0; i < 8; i++)
#pragma unroll
                for (int j = 0; j < 8; j++)
                    acc[i][j] += a_f[i] * b_f[j];
        }
        __syncthreads();
    }

#pragma unroll
    for (int i = 0; i < 8; i++) {
        float4 o0 = make_float4(acc[i][0], acc[i][1], acc[i][2], acc[i][3]);
        float4 o1 = make_float4(acc[i][4], acc[i][5], acc[i][6], acc[i][7]);
        float* cp = C + (size_t)(bm + ty * 8 + i) * N + bn + tx * 8;
        *(float4*)(cp)     = o0;
        *(float4*)(cp + 4) = o1;
    }
}

// ---------------------------------------------------------------------------
// RoPE (in place): pairs (d, d+32) within each head
// ---------------------------------------------------------------------------
__global__ void rope_kernel(float* __restrict__ X,
                            const float* __restrict__ ct,
                            const float* __restrict__ st, int heads)
{
    int i = blockIdx.x * blockDim.x + threadIdx.x;
    int total = BATCH * SEQ * heads * (HD / 2);
    if (i >= total) return;
    int d = i & 31;
    int r = i >> 5;
    int h = r % heads;
    int s = (r / heads) % SEQ;
    int b = r / (heads * SEQ);
    float* p = X + (((size_t)(b * SEQ + s) * heads) + h) * HD;
    float c  = ct[s * 32 + d];
    float sn = st[s * 32 + d];
    float x1 = p[d], x2 = p[d + 32];
    p[d]      = x1 * c - x2 * sn;
    p[d + 32] = x2 * c + x1 * sn;
}

// ---------------------------------------------------------------------------
// Flash-style attention. One CTA = one (b, h, 64-row q block); 64 threads,
// 1 q row / thread with q[64]/o[64] in registers. Doc-block skip via sorted
// doc_ids (branch uniform per CTA).
// ---------------------------------------------------------------------------
__global__ __launch_bounds__(64) void attn_kernel(const int* __restrict__ doc)
{
    __shared__ float q_s[64][65];     // pad 65: conflict-free row->reg copy
    __shared__ float k_s[64][64];
    __shared__ float v_s[64][64];
    __shared__ int   dk_s[64];

    const int t  = threadIdx.x;
    const int qb = blockIdx.x;
    const int h  = blockIdx.y;
    const int b  = blockIdx.z;
    const int kvh = h / NREP;
    const int q0 = qb * 64;

    // Stage Q tile (coalesced), copy own row to registers
    const float* Qb = g_Q + ((size_t)(b * SEQ + q0) * NH + h) * HD;
    for (int i = t; i < 64 * 64; i += 64) {
        int r = i >> 6, d = i & 63;
        q_s[r][d] = Qb[(size_t)r * NH * HD + d];
    }
    __syncthreads();

    float q_r[64];
#pragma unroll
    for (int d = 0; d < 64; d++) q_r[d] = q_s[t][d];

    const int doc_q    = doc[b * SEQ + q0 + t];
    const int doc_qmin = doc[b * SEQ + q0];

    float m = -1e30f, l = 0.0f;
    float o_r[64];
#pragma unroll
    for (int d = 0; d < 64; d++) o_r[d] = 0.0f;

    const float scale = 0.125f;                    // 1/sqrt(64)
    const float* Kb = g_K + ((size_t)(b * SEQ) * NKV + kvh) * HD;
    const float* Vb = g_V + ((size_t)(b * SEQ) * NKV + kvh) * HD;

    for (int kb = 0; kb <= qb; kb++) {
        int k0 = kb * 64;
        // block skip: all docs in k block < min doc in q block (uniform)
        if (doc[b * SEQ + k0 + 63] < doc_qmin) continue;

        __syncthreads();   // protect k_s/v_s reuse
        for (int i = t; i < 64 * 64; i += 64) {
            int r = i >> 6, d = i & 63;
            size_t off = (size_t)(k0 + r) * NKV * HD + d;
            k_s[r][d] = Kb[off];
            v_s[r][d] = Vb[off];
        }
        dk_s[t] = doc[b * SEQ + k0 + t];
        __syncthreads();

        const int jmax = (kb == qb) ? t : 63;      // causal limit

        for (int jb = 0; jb <= jmax; jb += 16) {
            float sc[16];
            float cmax = -1e30f;
#pragma unroll
            for (int jj = 0; jj < 16; jj++) {
                int j = jb + jj;
                float s;
                if (j > jmax || dk_s[j] != doc_q) {
                    s = -3.0e38f;
                } else {
                    const float4* kr = (const float4*)k_s[j];
                    float s0 = 0, s1 = 0, s2 = 0, s3 = 0;
#pragma unroll
                    for (int d4 = 0; d4 < 16; d4++) {
                        float4 kv = kr[d4];
                        s0 += q_r[d4 * 4 + 0] * kv.x;
                        s1 += q_r[d4 * 4 + 1] * kv.y;
                        s2 += q_r[d4 * 4 + 2] * kv.z;
                        s3 += q_r[d4 * 4 + 3] * kv.w;
                    }
                    s = ((s0 + s1) + (s2 + s3)) * scale;
                }
                sc[jj] = s;
                cmax = fmaxf(cmax, s);
            }

            if (cmax > m) {                         // one rescale per 16 keys
                float m_new = cmax;
                float alpha = __expf(m - m_new);
                l *= alpha;
#pragma unroll
                for (int d = 0; d < 64; d++) o_r[d] *= alpha;
                m = m_new;
            }

#pragma unroll
            for (int jj = 0; jj < 16; jj++) {
                float s = sc[jj];
                if (s > -1e37f) {
                    float p = __expf(s - m);
                    l += p;
                    const float4* vr = (const float4*)v_s[jb + jj];
#pragma unroll
                    for (int d4 = 0; d4 < 16; d4++) {
                        float4 vv = vr[d4];
                        o_r[d4 * 4 + 0] += p * vv.x;
                        o_r[d4 * 4 + 1] += p * vv.y;
                        o_r[d4 * 4 + 2] += p * vv.z;
                        o_r[d4 * 4 + 3] += p * vv.w;
                    }
                }
            }
        }
    }

    float inv_l = 1.0f / l;
    float* Ob = g_A + ((size_t)(b * SEQ + q0 + t)) * (NH * HD) + h * HD;
#pragma unroll
    for (int d4 = 0; d4 < 16; d4++) {
        float4 ov = make_float4(o_r[d4 * 4 + 0] * inv_l, o_r[d4 * 4 + 1] * inv_l,
                                o_r[d4 * 4 + 2] * inv_l, o_r[d4 * 4 + 3] * inv_l);
        *(float4*)(Ob + d4 * 4) = ov;
    }
}

// ---------------------------------------------------------------------------
// Launch
// ---------------------------------------------------------------------------
extern "C" void kernel_launch(void* const* d_in, const int* in_sizes, int n_in,
                              void* d_out, int out_size)
{
    const float* x   = (const float*)d_in[0];
    const float* rc  = (const float*)d_in[1];
    const float* rs  = (const float*)d_in[2];
    const int*   doc = (const int*)d_in[3];
    const float* Wq  = (const float*)d_in[4];
    const float* Wk  = (const float*)d_in[5];
    const float* Wv  = (const float*)d_in[6];
    const float* Wo  = (const float*)d_in[7];
    float* out = (float*)d_out;

    float *Qp, *Kp, *Vp, *Ap;
    cudaGetSymbolAddress((void**)&Qp, g_Q);
    cudaGetSymbolAddress((void**)&Kp, g_K);
    cudaGetSymbolAddress((void**)&Vp, g_V);
    cudaGetSymbolAddress((void**)&Ap, g_A);

    const int M = BATCH * SEQ;   // 4096

    // QKV projections
    sgemm_nt<<<dim3((NH * HD) / BN, M / BM), 256>>>(x, Wq, Qp, M, NH * HD, DMODEL);
    sgemm_nt<<<dim3((NKV * HD) / BN, M / BM), 256>>>(x, Wk, Kp, M, NKV * HD, DMODEL);
    sgemm_nt<<<dim3((NKV * HD) / BN, M / BM), 256>>>(x, Wv, Vp, M, NKV * HD, DMODEL);

    // RoPE on Q and K
    int nq = BATCH * SEQ * NH * (HD / 2);
    rope_kernel<<<(nq + 255) / 256, 256>>>(Qp, rc, rs, NH);
    int nk = BATCH * SEQ * NKV * (HD / 2);
    rope_kernel<<<(nk + 255) / 256, 256>>>(Kp, rc, rs, NKV);

    // Attention
    attn_kernel<<<dim3(SEQ / 64, NH, BATCH), 64>>>(doc);

    // Output projection
    sgemm_nt<<<dim3(DMODEL / BN, M / BM), 256>>>(Ap, Wo, out, M, DMODEL, NH * HD);
}

// round 3
// speedup vs baseline: 1.3212x; 1.3212x over previous
#include <cuda_runtime.h>
#include <cstdint>
#include <math.h>

#define BATCH 2
#define SEQ   2048
#define DMODEL 2048
#define NH    32
#define NKV   8
#define HD    64
#define NREP  (NH / NKV)

// ---------------------------------------------------------------------------
// Scratch (device globals — no allocation allowed)
// ---------------------------------------------------------------------------
__device__ float g_Q[(size_t)BATCH * SEQ * NH * HD];    // [B,S,NH,HD]
__device__ float g_K[(size_t)BATCH * SEQ * NKV * HD];   // [B,S,NKV,HD]
__device__ float g_V[(size_t)BATCH * SEQ * NKV * HD];
__device__ float g_A[(size_t)BATCH * SEQ * NH * HD];    // attn output [B,S,NH*HD]

// ---------------------------------------------------------------------------
// tf32 mma.sync GEMM: C[M,N] = A[M,K] * B[N,K]^T  (row-major, K contiguous)
// 128x128 CTA tile, BK=32 floats, 256 threads = 8 warps of 64x32.
// Register-staged double buffering. RNA-rounded tf32 via +0x1000 on raw bits.
// M % 128 == 0, N % 128 == 0, K % 32 == 0.
// ---------------------------------------------------------------------------
#define BM 128
#define BN 128
#define BKF 32
#define SPITCH 36   // smem row pitch in floats (pad 4 to break conflicts)

#define MMA_TF32(c, a, b) \
    asm volatile("mma.sync.aligned.m16n8k8.row.col.f32.tf32.tf32.f32 " \
        "{%0,%1,%2,%3}, {%4,%5,%6,%7}, {%8,%9}, {%0,%1,%2,%3};" \
        : "+f"((c)[0]), "+f"((c)[1]), "+f"((c)[2]), "+f"((c)[3]) \
        : "r"((a)[0]), "r"((a)[1]), "r"((a)[2]), "r"((a)[3]), \
          "r"((b)[0]), "r"((b)[1]))

__device__ __forceinline__ uint32_t rna_tf32(float f) {
    // round-to-nearest(-away) into tf32: add half-ulp of the 13-bit-truncated
    // mantissa on the raw bits (sign-magnitude => works for negatives too).
    return __float_as_uint(f) + 0x1000u;
}

__device__ __forceinline__ void ldg_tile(const float* __restrict__ P, int K,
                                         int row0, int kt, int tid, uint4 v[4])
{
#pragma unroll
    for (int i = 0; i < 4; i++) {
        int f = tid + i * 256;
        int r = f >> 3;
        int c = (f & 7) << 2;
        float4 x = *(const float4*)(P + (size_t)(row0 + r) * K + kt * BKF + c);
        v[i].x = rna_tf32(x.x);
        v[i].y = rna_tf32(x.y);
        v[i].z = rna_tf32(x.z);
        v[i].w = rna_tf32(x.w);
    }
}

__global__ __launch_bounds__(256) void gemm_tf32_mma(
    const float* __restrict__ A, const float* __restrict__ B,
    float* __restrict__ C, int M, int N, int K)
{
    __shared__ float As[BM][SPITCH];
    __shared__ float Bs[BN][SPITCH];

    const int tid  = threadIdx.x;
    const int lane = tid & 31;
    const int wid  = tid >> 5;
    const int wm   = (wid & 1) * 64;    // warp M offset within CTA tile
    const int wn   = (wid >> 1) * 32;   // warp N offset
    const int bm   = blockIdx.y * BM;
    const int bn   = blockIdx.x * BN;
    const int g    = lane >> 2;         // group row / n col
    const int tk   = lane & 3;          // k sub-index

    float acc[4][4][4];
#pragma unroll
    for (int i = 0; i < 4; i++)
#pragma unroll
        for (int j = 0; j < 4; j++)
#pragma unroll
            for (int r = 0; r < 4; r++) acc[i][j][r] = 0.0f;

    const int NT = K / BKF;
    uint4 avr[4], bvr[4];
    ldg_tile(A, K, bm, 0, tid, avr);
    ldg_tile(B, K, bn, 0, tid, bvr);

    for (int kt = 0; kt < NT; kt++) {
        __syncthreads();   // previous compute done before overwrite
#pragma unroll
        for (int i = 0; i < 4; i++) {
            int f = tid + i * 256;
            int r = f >> 3;
            int c = (f & 7) << 2;
            *(uint4*)&As[r][c] = avr[i];
        }
#pragma unroll
        for (int i = 0; i < 4; i++) {
            int f = tid + i * 256;
            int r = f >> 3;
            int c = (f & 7) << 2;
            *(uint4*)&Bs[r][c] = bvr[i];
        }
        __syncthreads();

        if (kt + 1 < NT) {   // issue next tile's LDGs; they drain during compute
            ldg_tile(A, K, bm, kt + 1, tid, avr);
            ldg_tile(B, K, bn, kt + 1, tid, bvr);
        }

#pragma unroll
        for (int ks = 0; ks < 4; ks++) {
            const int k0 = ks * 8;
            uint32_t af[4][4], bf[4][2];
#pragma unroll
            for (int mi = 0; mi < 4; mi++) {
                const int r0 = wm + mi * 16 + g;
                af[mi][0] = __float_as_uint(As[r0][k0 + tk]);
                af[mi][1] = __float_as_uint(As[r0 + 8][k0 + tk]);
                af[mi][2] = __float_as_uint(As[r0][k0 + tk + 4]);
                af[mi][3] = __float_as_uint(As[r0 + 8][k0 + tk + 4]);
            }
#pragma unroll
            for (int ni = 0; ni < 4; ni++) {
                const int n0 = wn + ni * 8 + g;
                bf[ni][0] = __float_as_uint(Bs[n0][k0 + tk]);
                bf[ni][1] = __float_as_uint(Bs[n0][k0 + tk + 4]);
            }
#pragma unroll
            for (int mi = 0; mi < 4; mi++)
#pragma unroll
                for (int ni = 0; ni < 4; ni++)
                    MMA_TF32(acc[mi][ni], af[mi], bf[ni]);
        }
    }

    // epilogue: c0,c1 at (row, 2tk), (row, 2tk+1); c2,c3 at row+8
#pragma unroll
    for (int mi = 0; mi < 4; mi++) {
        const int row = bm + wm + mi * 16 + g;
#pragma unroll
        for (int ni = 0; ni < 4; ni++) {
            const int col = bn + wn + ni * 8 + 2 * tk;
            float2 lo = make_float2(acc[mi][ni][0], acc[mi][ni][1]);
            float2 hi = make_float2(acc[mi][ni][2], acc[mi][ni][3]);
            *(float2*)(C + (size_t)row * N + col)       = lo;
            *(float2*)(C + (size_t)(row + 8) * N + col) = hi;
        }
    }
}

// ---------------------------------------------------------------------------
// RoPE (in place): pairs (d, d+32) within each head
// ---------------------------------------------------------------------------
__global__ void rope_kernel(float* __restrict__ X,
                            const float* __restrict__ ct,
                            const float* __restrict__ st, int heads)
{
    int i = blockIdx.x * blockDim.x + threadIdx.x;
    int total = BATCH * SEQ * heads * (HD / 2);
    if (i >= total) return;
    int d = i & 31;
    int r = i >> 5;
    int h = r % heads;
    int s = (r / heads) % SEQ;
    int b = r / (heads * SEQ);
    float* p = X + (((size_t)(b * SEQ + s) * heads) + h) * HD;
    float c  = ct[s * 32 + d];
    float sn = st[s * 32 + d];
    float x1 = p[d], x2 = p[d + 32];
    p[d]      = x1 * c - x2 * sn;
    p[d + 32] = x2 * c + x1 * sn;
}

// ---------------------------------------------------------------------------
// Flash-style attention. One CTA = one (b, h, 64-row q block); 64 threads,
// 1 q row / thread with q[64]/o[64] in registers. Doc-block skip via sorted
// doc_ids (branch uniform per CTA).
// ---------------------------------------------------------------------------
__global__ __launch_bounds__(64) void attn_kernel(const int* __restrict__ doc)
{
    __shared__ float q_s[64][65];
    __shared__ float k_s[64][64];
    __shared__ float v_s[64][64];
    __shared__ int   dk_s[64];

    const int t  = threadIdx.x;
    const int qb = blockIdx.x;
    const int h  = blockIdx.y;
    const int b  = blockIdx.z;
    const int kvh = h / NREP;
    const int q0 = qb * 64;

    const float* Qb = g_Q + ((size_t)(b * SEQ + q0) * NH + h) * HD;
    for (int i = t; i < 64 * 64; i += 64) {
        int r = i >> 6, d = i & 63;
        q_s[r][d] = Qb[(size_t)r * NH * HD + d];
    }
    __syncthreads();

    float q_r[64];
#pragma unroll
    for (int d = 0; d < 64; d++) q_r[d] = q_s[t][d];

    const int doc_q    = doc[b * SEQ + q0 + t];
    const int doc_qmin = doc[b * SEQ + q0];

    float m = -1e30f, l = 0.0f;
    float o_r[64];
#pragma unroll
    for (int d = 0; d < 64; d++) o_r[d] = 0.0f;

    const float scale = 0.125f;
    const float* Kb = g_K + ((size_t)(b * SEQ) * NKV + kvh) * HD;
    const float* Vb = g_V + ((size_t)(b * SEQ) * NKV + kvh) * HD;

    for (int kb = 0; kb <= qb; kb++) {
        int k0 = kb * 64;
        if (doc[b * SEQ + k0 + 63] < doc_qmin) continue;

        __syncthreads();
        for (int i = t; i < 64 * 64; i += 64) {
            int r = i >> 6, d = i & 63;
            size_t off = (size_t)(k0 + r) * NKV * HD + d;
            k_s[r][d] = Kb[off];
            v_s[r][d] = Vb[off];
        }
        dk_s[t] = doc[b * SEQ + k0 + t];
        __syncthreads();

        const int jmax = (kb == qb) ? t : 63;

        for (int jb = 0; jb <= jmax; jb += 16) {
            float sc[16];
            float cmax = -1e30f;
#pragma unroll
            for (int jj = 0; jj < 16; jj++) {
                int j = jb + jj;
                float s;
                if (j > jmax || dk_s[j] != doc_q) {
                    s = -3.0e38f;
                } else {
                    const float4* kr = (const float4*)k_s[j];
                    float s0 = 0, s1 = 0, s2 = 0, s3 = 0;
#pragma unroll
                    for (int d4 = 0; d4 < 16; d4++) {
                        float4 kv = kr[d4];
                        s0 += q_r[d4 * 4 + 0] * kv.x;
                        s1 += q_r[d4 * 4 + 1] * kv.y;
                        s2 += q_r[d4 * 4 + 2] * kv.z;
                        s3 += q_r[d4 * 4 + 3] * kv.w;
                    }
                    s = ((s0 + s1) + (s2 + s3)) * scale;
                }
                sc[jj] = s;
                cmax = fmaxf(cmax, s);
            }

            if (cmax > m) {
                float m_new = cmax;
                float alpha = __expf(m - m_new);
                l *= alpha;
#pragma unroll
                for (int d = 0; d < 64; d++) o_r[d] *= alpha;
                m = m_new;
            }

#pragma unroll
            for (int jj = 0; jj < 16; jj++) {
                float s = sc[jj];
                if (s > -1e37f) {
                    float p = __expf(s - m);
                    l += p;
                    const float4* vr = (const float4*)v_s[jb + jj];
#pragma unroll
                    for (int d4 = 0; d4 < 16; d4++) {
                        float4 vv = vr[d4];
                        o_r[d4 * 4 + 0] += p * vv.x;
                        o_r[d4 * 4 + 1] += p * vv.y;
                        o_r[d4 * 4 + 2] += p * vv.z;
                        o_r[d4 * 4 + 3] += p * vv.w;
                    }
                }
            }
        }
    }

    float inv_l = 1.0f / l;
    float* Ob = g_A + ((size_t)(b * SEQ + q0 + t)) * (NH * HD) + h * HD;
#pragma unroll
    for (int d4 = 0; d4 < 16; d4++) {
        float4 ov = make_float4(o_r[d4 * 4 + 0] * inv_l, o_r[d4 * 4 + 1] * inv_l,
                                o_r[d4 * 4 + 2] * inv_l, o_r[d4 * 4 + 3] * inv_l);
        *(float4*)(Ob + d4 * 4) = ov;
    }
}

// ---------------------------------------------------------------------------
// Launch
// ---------------------------------------------------------------------------
extern "C" void kernel_launch(void* const* d_in, const int* in_sizes, int n_in,
                              void* d_out, int out_size)
{
    const float* x   = (const float*)d_in[0];
    const float* rc  = (const float*)d_in[1];
    const float* rs  = (const float*)d_in[2];
    const int*   doc = (const int*)d_in[3];
    const float* Wq  = (const float*)d_in[4];
    const float* Wk  = (const float*)d_in[5];
    const float* Wv  = (const float*)d_in[6];
    const float* Wo  = (const float*)d_in[7];
    float* out = (float*)d_out;

    float *Qp, *Kp, *Vp, *Ap;
    cudaGetSymbolAddress((void**)&Qp, g_Q);
    cudaGetSymbolAddress((void**)&Kp, g_K);
    cudaGetSymbolAddress((void**)&Vp, g_V);
    cudaGetSymbolAddress((void**)&Ap, g_A);

    const int M = BATCH * SEQ;   // 4096

    // QKV projections (tf32 mma.sync)
    gemm_tf32_mma<<<dim3((NH * HD) / BN, M / BM), 256>>>(x, Wq, Qp, M, NH * HD, DMODEL);
    gemm_tf32_mma<<<dim3((NKV * HD) / BN, M / BM), 256>>>(x, Wk, Kp, M, NKV * HD, DMODEL);
    gemm_tf32_mma<<<dim3((NKV * HD) / BN, M / BM), 256>>>(x, Wv, Vp, M, NKV * HD, DMODEL);

    // RoPE on Q and K
    int nq = BATCH * SEQ * NH * (HD / 2);
    rope_kernel<<<(nq + 255) / 256, 256>>>(Qp, rc, rs, NH);
    int nk = BATCH * SEQ * NKV * (HD / 2);
    rope_kernel<<<(nk + 255) / 256, 256>>>(Kp, rc, rs, NKV);

    // Attention
    attn_kernel<<<dim3(SEQ / 64, NH, BATCH), 64>>>(doc);

    // Output projection (tf32 mma.sync)
    gemm_tf32_mma<<<dim3(DMODEL / BN, M / BM), 256>>>(Ap, Wo, out, M, DMODEL, NH * HD);
}

// round 6
// speedup vs baseline: 3.6230x; 2.7423x over previous
#include <cuda_runtime.h>
#include <cuda_fp16.h>
#include <cstdint>
#include <math.h>

#define BATCH 2
#define SEQ   2048
#define DMODEL 2048
#define NH    32
#define NKV   8
#define HD    64
#define NREP  (NH / NKV)

// ---------------------------------------------------------------------------
// Scratch (device globals — no allocation allowed)
// ---------------------------------------------------------------------------
__device__ float g_Q[(size_t)BATCH * SEQ * NH * HD];    // [B,S,NH,HD]
__device__ float g_K[(size_t)BATCH * SEQ * NKV * HD];   // [B,S,NKV,HD]
__device__ float g_V[(size_t)BATCH * SEQ * NKV * HD];
__device__ float g_A[(size_t)BATCH * SEQ * NH * HD];    // attn output [B,S,NH*HD]

__device__ __half g_xh [(size_t)BATCH * SEQ * DMODEL];
__device__ __half g_Wqh[(size_t)DMODEL * DMODEL];
__device__ __half g_Wkh[(size_t)NKV * HD * DMODEL];
__device__ __half g_Wvh[(size_t)NKV * HD * DMODEL];
__device__ __half g_Woh[(size_t)DMODEL * DMODEL];
__device__ __half g_Ah [(size_t)BATCH * SEQ * NH * HD];

// ---------------------------------------------------------------------------
// f32 -> f16 conversion (vectorized)
// ---------------------------------------------------------------------------
__global__ void f32_to_f16(const float4* __restrict__ in, __half2* __restrict__ out,
                           int n4)
{
    int i = blockIdx.x * blockDim.x + threadIdx.x;
    if (i >= n4) return;
    float4 v = in[i];
    out[2 * i]     = __floats2half2_rn(v.x, v.y);
    out[2 * i + 1] = __floats2half2_rn(v.z, v.w);
}

// ---------------------------------------------------------------------------
// f16 mma.sync GEMM: C[M,N] = A[M,K] * B[N,K]^T  (row-major, K contiguous)
// 128x128 CTA tile, BK=64 halves, 256 threads = 8 warps of 64x32.
// cp.async double buffer + ldmatrix fragments + mma.m16n8k16.
// M % 128 == 0, N % 128 == 0, K % 64 == 0.
// blockIdx.z selects (B0,C0) vs (B1,C1) so K/V projections share one launch.
// ---------------------------------------------------------------------------
#define RPITCH   144u            // bytes per smem row (64 halves + 8 pad)
#define A_BYTES  (128u * RPITCH) // 18432
#define STAGE_BYTES (2u * A_BYTES)
#define GEMM_SMEM (2u * STAGE_BYTES)   // 73728

#define CP16(dst, src) \
    asm volatile("cp.async.cg.shared.global [%0], [%1], 16;" :: "r"(dst), "l"(src))
#define CP_COMMIT() asm volatile("cp.async.commit_group;" ::)
#define CP_WAIT(n)  asm volatile("cp.async.wait_group %0;" :: "n"(n))

#define LDSM4(R, addr) \
    asm volatile("ldmatrix.sync.aligned.m8n8.x4.shared.b16 {%0,%1,%2,%3}, [%4];" \
        : "=r"((R)[0]), "=r"((R)[1]), "=r"((R)[2]), "=r"((R)[3]) : "r"(addr))

#define MMA16816(c, a, b0, b1) \
    asm volatile("mma.sync.aligned.m16n8k16.row.col.f32.f16.f16.f32 " \
        "{%0,%1,%2,%3}, {%4,%5,%6,%7}, {%8,%9}, {%0,%1,%2,%3};" \
        : "+f"((c)[0]), "+f"((c)[1]), "+f"((c)[2]), "+f"((c)[3]) \
        : "r"((a)[0]), "r"((a)[1]), "r"((a)[2]), "r"((a)[3]), "r"(b0), "r"(b1))

__device__ __forceinline__ uint32_t smem_u32(const void* p) {
    uint32_t a;
    asm("{ .reg .u64 t; cvta.to.shared.u64 t, %1; cvt.u32.u64 %0, t; }"
        : "=r"(a) : "l"(p));
    return a;
}

__device__ __forceinline__ void ld_stage(const __half* __restrict__ A,
                                         const __half* __restrict__ B,
                                         int K, int bm, int bn, int kt, int tid,
                                         uint32_t sA, uint32_t sB)
{
    const int k0 = kt * 64;
#pragma unroll
    for (int i = 0; i < 4; i++) {
        int c = tid + i * 256;
        int r = c >> 3, ch = c & 7;
        CP16(sA + r * RPITCH + ch * 16, A + (size_t)(bm + r) * K + k0 + ch * 8);
        CP16(sB + r * RPITCH + ch * 16, B + (size_t)(bn + r) * K + k0 + ch * 8);
    }
}

__global__ __launch_bounds__(256) void gemm_f16(
    const __half* __restrict__ A,
    const __half* __restrict__ B0, const __half* __restrict__ B1,
    float* __restrict__ C0, float* __restrict__ C1,
    int M, int N, int K)
{
    extern __shared__ char smem[];
    const __half* B = blockIdx.z ? B1 : B0;
    float*        C = blockIdx.z ? C1 : C0;

    const uint32_t sbase = smem_u32(smem);
    const int tid  = threadIdx.x;
    const int lane = tid & 31;
    const int wid  = tid >> 5;
    const int wm   = (wid & 1) * 64;
    const int wn   = (wid >> 1) * 32;
    const int bm   = blockIdx.y * 128;
    const int bn   = blockIdx.x * 128;
    const int g    = lane >> 2;
    const int tk   = lane & 3;

    // ldmatrix per-lane address components
    const int laneA_row = lane & 15;
    const int laneA_col = (lane >> 4) << 3;          // 0 or 8 halves
    const int laneB_row = (lane & 7) + (((lane >> 4) & 1) << 3);
    const int laneB_col = ((lane >> 3) & 1) << 3;

    float acc[4][4][4];
#pragma unroll
    for (int i = 0; i < 4; i++)
#pragma unroll
        for (int j = 0; j < 4; j++)
#pragma unroll
            for (int r = 0; r < 4; r++) acc[i][j][r] = 0.0f;

    const int NT = K / 64;

    ld_stage(A, B, K, bm, bn, 0, tid, sbase, sbase + A_BYTES);
    CP_COMMIT();

    for (int kt = 0; kt < NT; kt++) {
        const uint32_t curA = sbase + (kt & 1) * STAGE_BYTES;
        const uint32_t curB = curA + A_BYTES;

        if (kt + 1 < NT) {
            const uint32_t nA = sbase + ((kt + 1) & 1) * STAGE_BYTES;
            ld_stage(A, B, K, bm, bn, kt + 1, tid, nA, nA + A_BYTES);
            CP_COMMIT();
            CP_WAIT(1);
        } else {
            CP_WAIT(0);
        }
        __syncthreads();

#pragma unroll
        for (int ks = 0; ks < 4; ks++) {
            uint32_t af[4][4], bf[2][4];
#pragma unroll
            for (int mi = 0; mi < 4; mi++)
                LDSM4(af[mi], curA + (wm + mi * 16 + laneA_row) * RPITCH
                                   + (ks * 16 + laneA_col) * 2);
#pragma unroll
            for (int np = 0; np < 2; np++)
                LDSM4(bf[np], curB + (wn + np * 16 + laneB_row) * RPITCH
                                   + (ks * 16 + laneB_col) * 2);
#pragma unroll
            for (int mi = 0; mi < 4; mi++)
#pragma unroll
                for (int ni = 0; ni < 4; ni++)
                    MMA16816(acc[mi][ni], af[mi],
                             bf[ni >> 1][(ni & 1) * 2], bf[ni >> 1][(ni & 1) * 2 + 1]);
        }
        __syncthreads();
    }

    // epilogue: c0,c1 at (row, 2tk), c2,c3 at (row+8, 2tk)
#pragma unroll
    for (int mi = 0; mi < 4; mi++) {
        const int row = bm + wm + mi * 16 + g;
#pragma unroll
        for (int ni = 0; ni < 4; ni++) {
            const int col = bn + wn + ni * 8 + 2 * tk;
            *(float2*)(C + (size_t)row * N + col) =
                make_float2(acc[mi][ni][0], acc[mi][ni][1]);
            *(float2*)(C + (size_t)(row + 8) * N + col) =
                make_float2(acc[mi][ni][2], acc[mi][ni][3]);
        }
    }
}

// ---------------------------------------------------------------------------
// RoPE (in place): pairs (d, d+32) within each head
// ---------------------------------------------------------------------------
__global__ void rope_kernel(float* __restrict__ X,
                            const float* __restrict__ ct,
                            const float* __restrict__ st, int heads)
{
    int i = blockIdx.x * blockDim.x + threadIdx.x;
    int total = BATCH * SEQ * heads * (HD / 2);
    if (i >= total) return;
    int d = i & 31;
    int r = i >> 5;
    int h = r % heads;
    int s = (r / heads) % SEQ;
    int b = r / (heads * SEQ);
    float* p = X + (((size_t)(b * SEQ + s) * heads) + h) * HD;
    float c  = ct[s * 32 + d];
    float sn = st[s * 32 + d];
    float x1 = p[d], x2 = p[d + 32];
    p[d]      = x1 * c - x2 * sn;
    p[d + 32] = x2 * c + x1 * sn;
}

// ---------------------------------------------------------------------------
// Flash-style attention (unchanged). One CTA = one (b, h, 64-row q block).
// ---------------------------------------------------------------------------
__global__ __launch_bounds__(64) void attn_kernel(const int* __restrict__ doc)
{
    __shared__ float q_s[64][65];
    __shared__ float k_s[64][64];
    __shared__ float v_s[64][64];
    __shared__ int   dk_s[64];

    const int t  = threadIdx.x;
    const int qb = blockIdx.x;
    const int h  = blockIdx.y;
    const int b  = blockIdx.z;
    const int kvh = h / NREP;
    const int q0 = qb * 64;

    const float* Qb = g_Q + ((size_t)(b * SEQ + q0) * NH + h) * HD;
    for (int i = t; i < 64 * 64; i += 64) {
        int r = i >> 6, d = i & 63;
        q_s[r][d] = Qb[(size_t)r * NH * HD + d];
    }
    __syncthreads();

    float q_r[64];
#pragma unroll
    for (int d = 0; d < 64; d++) q_r[d] = q_s[t][d];

    const int doc_q    = doc[b * SEQ + q0 + t];
    const int doc_qmin = doc[b * SEQ + q0];

    float m = -1e30f, l = 0.0f;
    float o_r[64];
#pragma unroll
    for (int d = 0; d < 64; d++) o_r[d] = 0.0f;

    const float scale = 0.125f;
    const float* Kb = g_K + ((size_t)(b * SEQ) * NKV + kvh) * HD;
    const float* Vb = g_V + ((size_t)(b * SEQ) * NKV + kvh) * HD;

    for (int kb = 0; kb <= qb; kb++) {
        int k0 = kb * 64;
        if (doc[b * SEQ + k0 + 63] < doc_qmin) continue;

        __syncthreads();
        for (int i = t; i < 64 * 64; i += 64) {
            int r = i >> 6, d = i & 63;
            size_t off = (size_t)(k0 + r) * NKV * HD + d;
            k_s[r][d] = Kb[off];
            v_s[r][d] = Vb[off];
        }
        dk_s[t] = doc[b * SEQ + k0 + t];
        __syncthreads();

        const int jmax = (kb == qb) ? t : 63;

        for (int jb = 0; jb <= jmax; jb += 16) {
            float sc[16];
            float cmax = -1e30f;
#pragma unroll
            for (int jj = 0; jj < 16; jj++) {
                int j = jb + jj;
                float s;
                if (j > jmax || dk_s[j] != doc_q) {
                    s = -3.0e38f;
                } else {
                    const float4* kr = (const float4*)k_s[j];
                    float s0 = 0, s1 = 0, s2 = 0, s3 = 0;
#pragma unroll
                    for (int d4 = 0; d4 < 16; d4++) {
                        float4 kv = kr[d4];
                        s0 += q_r[d4 * 4 + 0] * kv.x;
                        s1 += q_r[d4 * 4 + 1] * kv.y;
                        s2 += q_r[d4 * 4 + 2] * kv.z;
                        s3 += q_r[d4 * 4 + 3] * kv.w;
                    }
                    s = ((s0 + s1) + (s2 + s3)) * scale;
                }
                sc[jj] = s;
                cmax = fmaxf(cmax, s);
            }

            if (cmax > m) {
                float m_new = cmax;
                float alpha = __expf(m - m_new);
                l *= alpha;
#pragma unroll
                for (int d = 0; d < 64; d++) o_r[d] *= alpha;
                m = m_new;
            }

#pragma unroll
            for (int jj = 0; jj < 16; jj++) {
                float s = sc[jj];
                if (s > -1e37f) {
                    float p = __expf(s - m);
                    l += p;
                    const float4* vr = (const float4*)v_s[jb + jj];
#pragma unroll
                    for (int d4 = 0; d4 < 16; d4++) {
                        float4 vv = vr[d4];
                        o_r[d4 * 4 + 0] += p * vv.x;
                        o_r[d4 * 4 + 1] += p * vv.y;
                        o_r[d4 * 4 + 2] += p * vv.z;
                        o_r[d4 * 4 + 3] += p * vv.w;
                    }
                }
            }
        }
    }

    float inv_l = 1.0f / l;
    float* Ob = g_A + ((size_t)(b * SEQ + q0 + t)) * (NH * HD) + h * HD;
#pragma unroll
    for (int d4 = 0; d4 < 16; d4++) {
        float4 ov = make_float4(o_r[d4 * 4 + 0] * inv_l, o_r[d4 * 4 + 1] * inv_l,
                                o_r[d4 * 4 + 2] * inv_l, o_r[d4 * 4 + 3] * inv_l);
        *(float4*)(Ob + d4 * 4) = ov;
    }
}

// ---------------------------------------------------------------------------
// Launch
// ---------------------------------------------------------------------------
extern "C" void kernel_launch(void* const* d_in, const int* in_sizes, int n_in,
                              void* d_out, int out_size)
{
    const float* x   = (const float*)d_in[0];
    const float* rc  = (const float*)d_in[1];
    const float* rs  = (const float*)d_in[2];
    const int*   doc = (const int*)d_in[3];
    const float* Wq  = (const float*)d_in[4];
    const float* Wk  = (const float*)d_in[5];
    const float* Wv  = (const float*)d_in[6];
    const float* Wo  = (const float*)d_in[7];
    float* out = (float*)d_out;

    float *Qp, *Kp, *Vp, *Ap;
    __half *xh, *wqh, *wkh, *wvh, *woh, *ah;
    cudaGetSymbolAddress((void**)&Qp, g_Q);
    cudaGetSymbolAddress((void**)&Kp, g_K);
    cudaGetSymbolAddress((void**)&Vp, g_V);
    cudaGetSymbolAddress((void**)&Ap, g_A);
    cudaGetSymbolAddress((void**)&xh, g_xh);
    cudaGetSymbolAddress((void**)&wqh, g_Wqh);
    cudaGetSymbolAddress((void**)&wkh, g_Wkh);
    cudaGetSymbolAddress((void**)&wvh, g_Wvh);
    cudaGetSymbolAddress((void**)&woh, g_Woh);
    cudaGetSymbolAddress((void**)&ah, g_Ah);

    cudaFuncSetAttribute(gemm_f16, cudaFuncAttributeMaxDynamicSharedMemorySize,
                         GEMM_SMEM);

    const int M = BATCH * SEQ;   // 4096

    // f32 -> f16 conversions
    {
        int n4;
        n4 = M * DMODEL / 4;
        f32_to_f16<<<(n4 + 255) / 256, 256>>>((const float4*)x, (__half2*)xh, n4);
        n4 = DMODEL * DMODEL / 4;
        f32_to_f16<<<(n4 + 255) / 256, 256>>>((const float4*)Wq, (__half2*)wqh, n4);
        n4 = NKV * HD * DMODEL / 4;
        f32_to_f16<<<(n4 + 255) / 256, 256>>>((const float4*)Wk, (__half2*)wkh, n4);
        f32_to_f16<<<(n4 + 255) / 256, 256>>>((const float4*)Wv, (__half2*)wvh, n4);
        n4 = DMODEL * DMODEL / 4;
        f32_to_f16<<<(n4 + 255) / 256, 256>>>((const float4*)Wo, (__half2*)woh, n4);
    }

    // Q projection
    gemm_f16<<<dim3((NH * HD) / 128, M / 128, 1), 256, GEMM_SMEM>>>(
        xh, wqh, wqh, Qp, Qp, M, NH * HD, DMODEL);
    // K and V projections fused via blockIdx.z
    gemm_f16<<<dim3((NKV * HD) / 128, M / 128, 2), 256, GEMM_SMEM>>>(
        xh, wkh, wvh, Kp, Vp, M, NKV * HD, DMODEL);

    // RoPE on Q and K
    int nq = BATCH * SEQ * NH * (HD / 2);
    rope_kernel<<<(nq + 255) / 256, 256>>>(Qp, rc, rs, NH);
    int nk = BATCH * SEQ * NKV * (HD / 2);
    rope_kernel<<<(nk + 255) / 256, 256>>>(Kp, rc, rs, NKV);

    // Attention
    attn_kernel<<<dim3(SEQ / 64, NH, BATCH), 64>>>(doc);

    // Attention output -> f16, then output projection
    {
        int n4 = M * NH * HD / 4;
        f32_to_f16<<<(n4 + 255) / 256, 256>>>((const float4*)Ap, (__half2*)ah, n4);
    }
    gemm_f16<<<dim3(DMODEL / 128, M / 128, 1), 256, GEMM_SMEM>>>(
        ah, woh, woh, out, out, M, DMODEL, NH * HD);
}